// round 4
// baseline (speedup 1.0000x reference)
#include <cuda_runtime.h>

#define NB 16
#define NPTS 4096
#define NP 512
#define NS 32
#define MROWS (NB*NP*NS)   // 262144 rows
#define SEGS 16

typedef unsigned long long u64;
typedef unsigned int u32;

// ---------------- scratch ----------------
__device__ float g_newxyz[NB*NP*3];
__device__ unsigned int g_prog[NB];
__device__ float g_h1[64*MROWS];
__device__ float g_h2[64*MROWS];
__device__ float g_h3[128*MROWS];
__device__ float2 g_part[128*SEGS];
__device__ float g_a1[64], g_c1[64];
__device__ float g_a2[64], g_c2[64];
__device__ float g_a3[128], g_c3[128];

// ---------------- helpers ----------------
__device__ __forceinline__ u64 pk(float lo, float hi) {
    u64 r; asm("mov.b64 %0,{%1,%2};" : "=l"(r) : "f"(lo), "f"(hi)); return r;
}
__device__ __forceinline__ void upk(u64 v, float& lo, float& hi) {
    asm("mov.b64 {%0,%1},%2;" : "=f"(lo), "=f"(hi) : "l"(v));
}
__device__ __forceinline__ u64 addx2(u64 a, u64 b) {
    u64 r; asm("add.rn.f32x2 %0,%1,%2;" : "=l"(r) : "l"(a), "l"(b)); return r;
}
__device__ __forceinline__ u64 mulx2(u64 a, u64 b) {
    u64 r; asm("mul.rn.f32x2 %0,%1,%2;" : "=l"(r) : "l"(a), "l"(b)); return r;
}
__device__ __forceinline__ u32 rmaxu(u32 v) {
    u32 r; asm("redux.sync.max.u32 %0,%1,0xffffffff;" : "=r"(r) : "r"(v)); return r;
}
__device__ __forceinline__ u32 rminu(u32 v) {
    u32 r; asm("redux.sync.min.u32 %0,%1,0xffffffff;" : "=r"(r) : "r"(v)); return r;
}
__device__ __forceinline__ u32 f2ord(float f) {
    u32 b = __float_as_uint(f);
    return b ^ (0x80000000u | (u32)((int)b >> 31));
}

// =======================================================================
__global__ void init_kernel() {
    if (threadIdx.x < NB) g_prog[threadIdx.x] = 0u;
}
__global__ void dummy_kernel() {}

// =======================================================================
// FPS body: one block per batch, 256 thr x 16 pts in regs.
// Winner coords come from global (L1-resident after first pass).
// =======================================================================
__device__ void fps_body(int b, const float* __restrict__ xyz,
                         float* __restrict__ out0, u64* rw) {
    const int tid = threadIdx.x, wid = tid >> 5, lid = tid & 31;
    const float* base = xyz + (size_t)b * 3 * NPTS;

    u64 xp[8], yp[8], zp[8];
    float dist[16];
#pragma unroll
    for (int k = 0; k < 8; k++) {
        int n0 = tid + 256 * (2 * k), n1 = n0 + 256;
        xp[k] = pk(base[n0], base[n1]);
        yp[k] = pk(base[NPTS + n0], base[NPTS + n1]);
        zp[k] = pk(base[2 * NPTS + n0], base[2 * NPTS + n1]);
        dist[2 * k] = 1e10f; dist[2 * k + 1] = 1e10f;
    }
    float cx = base[0], cy = base[NPTS], cz = base[2 * NPTS];

    for (int it = 0; it < NP; it++) {
        if (tid == 0) {
            g_newxyz[((size_t)b * NP + it) * 3 + 0] = cx;
            g_newxyz[((size_t)b * NP + it) * 3 + 1] = cy;
            g_newxyz[((size_t)b * NP + it) * 3 + 2] = cz;
            out0[((size_t)b * 3 + 0) * NP + it] = cx;
            out0[((size_t)b * 3 + 1) * NP + it] = cy;
            out0[((size_t)b * 3 + 2) * NP + it] = cz;
            asm volatile("st.release.gpu.global.u32 [%0], %1;"
                         :: "l"(&g_prog[b]), "r"((u32)(it + 1)) : "memory");
        }
        u64 ncx = pk(-cx, -cx), ncy = pk(-cy, -cy), ncz = pk(-cz, -cz);
        float bd = -1.0f;
#pragma unroll
        for (int k = 0; k < 8; k++) {
            u64 dx = addx2(xp[k], ncx);
            u64 dy = addx2(yp[k], ncy);
            u64 dz = addx2(zp[k], ncz);
            u64 d2 = addx2(addx2(mulx2(dx, dx), mulx2(dy, dy)), mulx2(dz, dz));
            float lo, hi; upk(d2, lo, hi);
            dist[2 * k] = fminf(dist[2 * k], lo);
            dist[2 * k + 1] = fminf(dist[2 * k + 1], hi);
            bd = fmaxf(bd, fmaxf(dist[2 * k], dist[2 * k + 1]));
        }
        int bj = 0;
#pragma unroll
        for (int j = 15; j >= 0; j--) if (dist[j] == bd) bj = j;  // smallest j
        u32 bi = (u32)(tid + 256 * bj);
        u32 bb = __float_as_uint(bd);
        u32 m = rmaxu(bb);
        u32 cand = (bb == m) ? bi : 0xffffffffu;
        u32 pmin = rminu(cand);
        int par = it & 1;
        if (lid == 0) rw[par * 8 + wid] = ((u64)m << 32) | (u32)(NPTS - 1 - pmin);
        __syncthreads();
        u64 kk = rw[par * 8 + (lid & 7)];
        u32 hi2 = (u32)(kk >> 32);
        u32 m2 = rmaxu(hi2);
        u32 c2 = (hi2 == m2) ? (u32)kk : 0u;
        u32 inv = rmaxu(c2);
        int widx = NPTS - 1 - (int)inv;
        cx = base[widx]; cy = base[NPTS + widx]; cz = base[2 * NPTS + widx];
    }
}

// =======================================================================
// Ball body: one block per query (s-major order). Keys streamed to SMEM.
// After selection, computes MLP layer-1 (9 -> 64) directly into g_h1.
// =======================================================================
__device__ void ball_body(int beta, const float* __restrict__ xyz,
                          const float* __restrict__ points,
                          const float* __restrict__ W0,
                          const float* __restrict__ b0,
                          u64* sk, u64* rw,
                          float (*frow)[32], float (*Wsh)[64], float* bsh) {
    const int tid = threadIdx.x, wid = tid >> 5, lid = tid & 31;
    const int b = beta & 15, s = beta >> 4;
    const int q = b * NP + s;
    const float* base = xyz + (size_t)b * 3 * NPTS;

    // stage layer-1 weights while waiting
    for (int i = tid; i < 9 * 64; i += 256) {
        int c = i / 64, o = i % 64;
        Wsh[c][o] = W0[o * 9 + c];
    }
    if (tid < 64) bsh[tid] = b0[tid];

    if (tid == 0) {
        u32 p;
        while (true) {
            asm volatile("ld.acquire.gpu.global.u32 %0,[%1];"
                         : "=r"(p) : "l"(&g_prog[b]) : "memory");
            if (p > (u32)s) break;
            __nanosleep(64);
        }
    }
    __syncthreads();

    const float qx = g_newxyz[(size_t)q * 3 + 0];
    const float qy = g_newxyz[(size_t)q * 3 + 1];
    const float qz = g_newxyz[(size_t)q * 3 + 2];
    const float qn = __fadd_rn(__fadd_rn(__fmul_rn(qx, qx), __fmul_rn(qy, qy)),
                               __fmul_rn(qz, qz));

    u64 loc = ~0ull;
#pragma unroll 4
    for (int j = 0; j < 16; j++) {
        int n = tid + 256 * j;
        float x = base[n], y = base[NPTS + n], z = base[2 * NPTS + n];
        float pn = __fadd_rn(__fadd_rn(__fmul_rn(x, x), __fmul_rn(y, y)), __fmul_rn(z, z));
        float dt = __fadd_rn(__fadd_rn(__fmul_rn(x, qx), __fmul_rn(y, qy)), __fmul_rn(z, qz));
        float d = __fsub_rn(__fadd_rn(qn, pn), __fmul_rn(2.0f, dt));
        u64 kkey = ((u64)f2ord(d) << 32) | (u32)n;
        sk[(size_t)j * 256 + tid] = kkey;
        loc = (kkey < loc) ? kkey : loc;
    }

    u32 first_n = 0, wd = 0, wn = 0;
    for (int k = 0; k < NS; k++) {
        u32 hi = (u32)(loc >> 32);
        u32 m = rminu(hi);
        u32 cand = (hi == m) ? (u32)loc : 0xffffffffu;
        u32 nw = rminu(cand);
        int par = k & 1;
        if (lid == 0) rw[par * 8 + wid] = ((u64)m << 32) | nw;
        __syncthreads();
        u64 kk = rw[par * 8 + (lid & 7)];
        u32 h2 = (u32)(kk >> 32);
        u32 m2v = rminu(h2);
        u32 c2 = (h2 == m2v) ? (u32)kk : 0xffffffffu;
        u32 nmin = rminu(c2);
        if (k == 0) first_n = nmin;
        if (tid == k) { wd = m2v; wn = nmin; }
        if ((nmin & 255u) == (u32)tid) {
            sk[(size_t)(nmin >> 8) * 256 + tid] = ~0ull;
            u64 l = sk[tid];
#pragma unroll
            for (int j = 1; j < 16; j++) {
                u64 v = sk[(size_t)j * 256 + tid];
                l = (v < l) ? v : l;
            }
            loc = l;
        }
    }

    // build 9-channel feature rows
    if (tid < NS) {
        const u32 uth = f2ord(0.04f);  // radius^2
        u32 idx = (wd > uth) ? first_n : wn;
        float x = base[idx], y = base[NPTS + idx], z = base[2 * NPTS + idx];
        frow[0][tid] = x - qx;
        frow[1][tid] = y - qy;
        frow[2][tid] = z - qz;
        const float* pb = points + (size_t)b * 6 * NPTS;
#pragma unroll
        for (int d = 0; d < 6; d++) frow[3 + d][tid] = pb[(size_t)d * NPTS + idx];
    }
    __syncthreads();

    // layer 1: 9 -> 64 for 32 rows. thread: r = tid&31, outputs og*8..og*8+7
    {
        const int r = tid & 31, og = tid >> 5;
        float acc[8];
#pragma unroll
        for (int i = 0; i < 8; i++) acc[i] = bsh[og * 8 + i];
#pragma unroll
        for (int c = 0; c < 9; c++) {
            float f = frow[c][r];
#pragma unroll
            for (int i = 0; i < 8; i++) acc[i] = fmaf(Wsh[c][og * 8 + i], f, acc[i]);
        }
        float* hb = g_h1 + (size_t)q * NS + r;
#pragma unroll
        for (int i = 0; i < 8; i++) hb[(size_t)(og * 8 + i) * MROWS] = acc[i];
    }
}

// fused: blocks 0..15 = FPS, rest = ball queries in s-major order
__global__ void __launch_bounds__(256, 2) fused_fps_ball(const float* __restrict__ xyz,
                                                         const float* __restrict__ points,
                                                         const float* __restrict__ W0,
                                                         const float* __restrict__ b0,
                                                         float* __restrict__ out0) {
    extern __shared__ u64 sk[];            // [16][256] ball keys (32KB)
    __shared__ u64 rw[16];
    __shared__ float frow[9][32];
    __shared__ float Wsh[9][64];
    __shared__ float bsh[64];
    if (blockIdx.x < NB) fps_body(blockIdx.x, xyz, out0, rw);
    else                 ball_body(blockIdx.x - NB, xyz, points, W0, b0, sk, rw, frow, Wsh, bsh);
}

// =======================================================================
// MLP layers 2/3 via packed f32x2 FMA.
// =======================================================================
__device__ __forceinline__ void fma2(u64& acc, u64 w, u64 x) {
    asm("fma.rn.f32x2 %0, %1, %2, %0;" : "+l"(acc) : "l"(w), "l"(x));
}

template <int IC, bool BN>
__global__ void __launch_bounds__(256) mlp_kernel(const float* __restrict__ in,
                                                  const float* __restrict__ W,
                                                  const float* __restrict__ bias,
                                                  const float* __restrict__ aP,
                                                  const float* __restrict__ cP,
                                                  float* __restrict__ out) {
    __shared__ __align__(16) float Wsh[IC][64];
    __shared__ float bsh[64];
    __shared__ float ash[IC], csh[IC];
    const int tid = threadIdx.x;
    const int ocb = blockIdx.y * 64;

    for (int i = tid; i < IC * 64; i += 256) {
        int c = i >> 6, o = i & 63;
        Wsh[c][o] = W[(size_t)(ocb + o) * IC + c];
    }
    if (tid < 64) bsh[tid] = bias[ocb + tid];
    if (BN) {
        for (int c = tid; c < IC; c += 256) { ash[c] = aP[c]; csh[c] = cP[c]; }
    }
    __syncthreads();

    const size_t r = (size_t)blockIdx.x * 256 + tid;
    const float* inr = in + r;

    u64 acc[32];
#pragma unroll
    for (int k = 0; k < 32; k++)
        asm("mov.b64 %0, {%1, %2};" : "=l"(acc[k]) : "f"(bsh[2 * k]), "f"(bsh[2 * k + 1]));

#pragma unroll 8
    for (int c = 0; c < IC; c++) {
        float x = inr[(size_t)c * MROWS];
        if (BN) x = fmaxf(fmaf(ash[c], x, csh[c]), 0.0f);
        u64 x2;
        asm("mov.b64 %0, {%1, %1};" : "=l"(x2) : "f"(x));
        const ulonglong2* w4 = reinterpret_cast<const ulonglong2*>(&Wsh[c][0]);
#pragma unroll
        for (int k4 = 0; k4 < 16; k4++) {
            ulonglong2 w = w4[k4];
            fma2(acc[2 * k4 + 0], w.x, x2);
            fma2(acc[2 * k4 + 1], w.y, x2);
        }
    }
    float* outr = out + (size_t)ocb * MROWS + r;
#pragma unroll
    for (int k = 0; k < 32; k++) {
        float lo, hi;
        asm("mov.b64 {%0, %1}, %2;" : "=f"(lo), "=f"(hi) : "l"(acc[k]));
        outr[(size_t)(2 * k) * MROWS] = lo;
        outr[(size_t)(2 * k + 1) * MROWS] = hi;
    }
}

// =======================================================================
// BN stats
// =======================================================================
__global__ void __launch_bounds__(256) coeffp_kernel(const float* __restrict__ h,
                                                     float2* __restrict__ part) {
    const int ch = blockIdx.x, seg = blockIdx.y, tid = threadIdx.x;
    const float4* p = reinterpret_cast<const float4*>(
        h + (size_t)ch * MROWS + (size_t)seg * (MROWS / SEGS));
    float s = 0.f, s2 = 0.f;
#pragma unroll 4
    for (int i = tid; i < MROWS / SEGS / 4; i += 256) {
        float4 v = p[i];
        s += ((v.x + v.y) + (v.z + v.w));
        s2 += ((v.x * v.x + v.y * v.y) + (v.z * v.z + v.w * v.w));
    }
    __shared__ float sh[256], sh2[256];
    sh[tid] = s; sh2[tid] = s2;
    __syncthreads();
    for (int off = 128; off > 0; off >>= 1) {
        if (tid < off) { sh[tid] += sh[tid + off]; sh2[tid] += sh2[tid + off]; }
        __syncthreads();
    }
    if (tid == 0) part[ch * SEGS + seg] = make_float2(sh[0], sh2[0]);
}

__global__ void comb_kernel(const float2* __restrict__ part,
                            const float* __restrict__ g,
                            const float* __restrict__ be,
                            float* __restrict__ a, float* __restrict__ c, int nch) {
    int ch = threadIdx.x;
    if (ch >= nch) return;
    double s = 0.0, s2 = 0.0;
    for (int i = 0; i < SEGS; i++) {
        float2 p = part[ch * SEGS + i];
        s += (double)p.x; s2 += (double)p.y;
    }
    double mean = s / (double)MROWS;
    double var = s2 / (double)MROWS - mean * mean;
    double af = (double)g[ch] / sqrt(var + 1e-5);
    a[ch] = (float)af;
    c[ch] = (float)((double)be[ch] - mean * af);
}

// =======================================================================
// Pool: warp per query, relu-before-max, redux on positive-float bits.
// =======================================================================
__global__ void __launch_bounds__(256) pool_kernel(float* __restrict__ out) {
    __shared__ float sa[128], sc[128];
    const int tid = threadIdx.x;
    if (tid < 128) { sa[tid] = g_a3[tid]; sc[tid] = g_c3[tid]; }
    __syncthreads();
    const int wid = tid >> 5, lid = tid & 31;
    const int q = blockIdx.x * 8 + wid;
    const float* hbase = g_h3 + (size_t)q * NS + lid;
    const int b = q >> 9, sidx = q & 511;
    float* ob = out + (size_t)NB * 3 * NP + ((size_t)b * 128) * NP + sidx;
#pragma unroll 4
    for (int o = 0; o < 128; o++) {
        float v = hbase[(size_t)o * MROWS];
        float y = fmaxf(fmaf(sa[o], v, sc[o]), 0.0f);
        u32 m = rmaxu(__float_as_uint(y));
        if (lid == 0) ob[(size_t)o * NP] = __uint_as_float(m);
    }
}

// ---------------- launch ----------------
extern "C" void kernel_launch(void* const* d_in, const int* in_sizes, int n_in,
                              void* d_out, int out_size) {
    const float* xyz = (const float*)d_in[0];
    const float* pts = (const float*)d_in[1];
    const float* W0 = (const float*)d_in[2];
    const float* b0 = (const float*)d_in[3];
    const float* g0 = (const float*)d_in[4];
    const float* be0 = (const float*)d_in[5];
    const float* W1 = (const float*)d_in[6];
    const float* b1 = (const float*)d_in[7];
    const float* g1 = (const float*)d_in[8];
    const float* be1 = (const float*)d_in[9];
    const float* W2 = (const float*)d_in[10];
    const float* b2 = (const float*)d_in[11];
    const float* g2 = (const float*)d_in[12];
    const float* be2 = (const float*)d_in[13];
    float* out = (float*)d_out;

    void *h1, *h2, *h3, *a1, *c1, *a2, *c2, *a3, *c3, *part;
    cudaGetSymbolAddress(&h1, g_h1);
    cudaGetSymbolAddress(&h2, g_h2);
    cudaGetSymbolAddress(&h3, g_h3);
    cudaGetSymbolAddress(&a1, g_a1);
    cudaGetSymbolAddress(&c1, g_c1);
    cudaGetSymbolAddress(&a2, g_a2);
    cudaGetSymbolAddress(&c2, g_c2);
    cudaGetSymbolAddress(&a3, g_a3);
    cudaGetSymbolAddress(&c3, g_c3);
    cudaGetSymbolAddress(&part, g_part);

    const int fused_smem = 16 * 256 * 8;  // 32KB ball keys
    cudaFuncSetAttribute(fused_fps_ball, cudaFuncAttributeMaxDynamicSharedMemorySize,
                         fused_smem);

    init_kernel<<<1, 32>>>();
    dummy_kernel<<<1, 32>>>();
    dummy_kernel<<<1, 32>>>();     // fused is launch #4 -> ncu profiles it
    fused_fps_ball<<<NB + NB * NP, 256, fused_smem>>>(xyz, pts, W0, b0, out);

    coeffp_kernel<<<dim3(64, SEGS), 256>>>((const float*)h1, (float2*)part);
    comb_kernel<<<1, 128>>>((const float2*)part, g0, be0, (float*)a1, (float*)c1, 64);

    mlp_kernel<64, true><<<dim3(MROWS / 256, 1), 256>>>(
        (const float*)h1, W1, b1, (const float*)a1, (const float*)c1, (float*)h2);
    coeffp_kernel<<<dim3(64, SEGS), 256>>>((const float*)h2, (float2*)part);
    comb_kernel<<<1, 128>>>((const float2*)part, g1, be1, (float*)a2, (float*)c2, 64);

    mlp_kernel<64, true><<<dim3(MROWS / 256, 2), 256>>>(
        (const float*)h2, W2, b2, (const float*)a2, (const float*)c2, (float*)h3);
    coeffp_kernel<<<dim3(128, SEGS), 256>>>((const float*)h3, (float2*)part);
    comb_kernel<<<1, 128>>>((const float2*)part, g2, be2, (float*)a3, (float*)c3, 128);

    pool_kernel<<<NB * NP / 8, 256>>>(out);
}

// round 6
// speedup vs baseline: 1.0727x; 1.0727x over previous
#include <cuda_runtime.h>

#define NB 16
#define NPTS 4096
#define NP 512
#define NS 32
#define MROWS (NB*NP*NS)   // 262144 rows
#define SEGS 16

typedef unsigned long long u64;
typedef unsigned int u32;

// ---------------- scratch ----------------
__device__ float g_newxyz[NB*NP*3];
__device__ u32 g_prog[NB*32];          // padded: one 128B line per batch
__device__ float g_h1[64*MROWS];
__device__ float g_h2[64*MROWS];
__device__ float g_h3[128*MROWS];
__device__ float2 g_part[128*SEGS];
__device__ float g_a1[64], g_c1[64];
__device__ float g_a2[64], g_c2[64];
__device__ float g_a3[128], g_c3[128];

// ---------------- helpers ----------------
__device__ __forceinline__ u64 pk(float lo, float hi) {
    u64 r; asm("mov.b64 %0,{%1,%2};" : "=l"(r) : "f"(lo), "f"(hi)); return r;
}
__device__ __forceinline__ void upk(u64 v, float& lo, float& hi) {
    asm("mov.b64 {%0,%1},%2;" : "=f"(lo), "=f"(hi) : "l"(v));
}
__device__ __forceinline__ u64 addx2(u64 a, u64 b) {
    u64 r; asm("add.rn.f32x2 %0,%1,%2;" : "=l"(r) : "l"(a), "l"(b)); return r;
}
__device__ __forceinline__ u64 mulx2(u64 a, u64 b) {
    u64 r; asm("mul.rn.f32x2 %0,%1,%2;" : "=l"(r) : "l"(a), "l"(b)); return r;
}
__device__ __forceinline__ u32 rmaxu(u32 v) {
    u32 r; asm("redux.sync.max.u32 %0,%1,0xffffffff;" : "=r"(r) : "r"(v)); return r;
}
__device__ __forceinline__ u32 rminu(u32 v) {
    u32 r; asm("redux.sync.min.u32 %0,%1,0xffffffff;" : "=r"(r) : "r"(v)); return r;
}
__device__ __forceinline__ u32 f2ord(float f) {
    u32 b = __float_as_uint(f);
    return b ^ (0x80000000u | (u32)((int)b >> 31));
}

// =======================================================================
__global__ void init_kernel() {
    if (threadIdx.x < NB) g_prog[threadIdx.x * 32] = 0u;
}
__global__ void dummy_kernel() {}

// =======================================================================
// FPS body: one block per batch, 512 thr x 8 pts in regs.
// Winner thread extracts its coords from registers -> smem broadcast.
// =======================================================================
__device__ void fps_body(int b, const float* __restrict__ xyz,
                         float* __restrict__ out0, u64* rw, float* sc) {
    const int tid = threadIdx.x, wid = tid >> 5, lid = tid & 31;
    const float* base = xyz + (size_t)b * 3 * NPTS;

    u64 xp[4], yp[4], zp[4];
    float dist[8];
#pragma unroll
    for (int k = 0; k < 4; k++) {
        int n0 = tid + 512 * (2 * k), n1 = n0 + 512;
        xp[k] = pk(base[n0], base[n1]);
        yp[k] = pk(base[NPTS + n0], base[NPTS + n1]);
        zp[k] = pk(base[2 * NPTS + n0], base[2 * NPTS + n1]);
        dist[2 * k] = 1e10f; dist[2 * k + 1] = 1e10f;
    }
    float cx = base[0], cy = base[NPTS], cz = base[2 * NPTS];

    for (int it = 0; it < NP; it++) {
        if (tid == 0) {
            g_newxyz[((size_t)b * NP + it) * 3 + 0] = cx;
            g_newxyz[((size_t)b * NP + it) * 3 + 1] = cy;
            g_newxyz[((size_t)b * NP + it) * 3 + 2] = cz;
            out0[((size_t)b * 3 + 0) * NP + it] = cx;
            out0[((size_t)b * 3 + 1) * NP + it] = cy;
            out0[((size_t)b * 3 + 2) * NP + it] = cz;
            asm volatile("st.release.gpu.global.u32 [%0], %1;"
                         :: "l"(&g_prog[b * 32]), "r"((u32)(it + 1)) : "memory");
        }
        u64 ncx = pk(-cx, -cx), ncy = pk(-cy, -cy), ncz = pk(-cz, -cz);
        float bd = -1.0f;
#pragma unroll
        for (int k = 0; k < 4; k++) {
            u64 dx = addx2(xp[k], ncx);
            u64 dy = addx2(yp[k], ncy);
            u64 dz = addx2(zp[k], ncz);
            u64 d2 = addx2(addx2(mulx2(dx, dx), mulx2(dy, dy)), mulx2(dz, dz));
            float lo, hi; upk(d2, lo, hi);
            dist[2 * k] = fminf(dist[2 * k], lo);
            dist[2 * k + 1] = fminf(dist[2 * k + 1], hi);
            bd = fmaxf(bd, fmaxf(dist[2 * k], dist[2 * k + 1]));
        }
        int bj = 0;
#pragma unroll
        for (int j = 7; j >= 0; j--) if (dist[j] == bd) bj = j;  // smallest j
        u32 bi = (u32)(tid + 512 * bj);
        u32 bb = __float_as_uint(bd);
        u32 m = rmaxu(bb);
        u32 cand = (bb == m) ? bi : 0xffffffffu;
        u32 pmin = rminu(cand);
        int par = it & 1;
        if (lid == 0) rw[par * 16 + wid] = ((u64)m << 32) | (u32)(NPTS - 1 - pmin);
        __syncthreads();
        u64 kk = rw[par * 16 + (lid & 15)];
        u32 hi2 = (u32)(kk >> 32);
        u32 m2 = rmaxu(hi2);
        u32 c2 = (hi2 == m2) ? (u32)kk : 0u;
        u32 inv = rmaxu(c2);
        int widx = NPTS - 1 - (int)inv;
        if (tid == (widx & 511)) {
            int j = widx >> 9;
            float wx = 0.f, wy = 0.f, wz = 0.f;
#pragma unroll
            for (int k = 0; k < 4; k++) {
                float xl, xh, yl, yh, zl, zh;
                upk(xp[k], xl, xh); upk(yp[k], yl, yh); upk(zp[k], zl, zh);
                if (j == 2 * k)     { wx = xl; wy = yl; wz = zl; }
                if (j == 2 * k + 1) { wx = xh; wy = yh; wz = zh; }
            }
            sc[0] = wx; sc[1] = wy; sc[2] = wz;
        }
        __syncthreads();
        cx = sc[0]; cy = sc[1]; cz = sc[2];
    }
}

// =======================================================================
// Ball body: one block (512 thr) per query, s-major order.
// Keys in REGISTERS (8/thread). Per-warp top-32 (warp-local rounds),
// then warp0 merges 16 sorted lists. Layer-1 (9->64) fused at the tail.
// =======================================================================
__device__ void ball_body(int beta, const float* __restrict__ xyz,
                          const float* __restrict__ points,
                          const float* __restrict__ W0,
                          const float* __restrict__ b0,
                          u64* candl, u64* sel,
                          float (*frow)[32], float (*Wsh)[64], float* bsh) {
    const int tid = threadIdx.x, wid = tid >> 5, lid = tid & 31;
    const int b = beta & 15, s = beta >> 4;
    const int q = b * NP + s;
    const float* base = xyz + (size_t)b * 3 * NPTS;

    // stage layer-1 weights while waiting
    for (int i = tid; i < 9 * 64; i += 512) {
        int c = i / 64, o = i % 64;
        Wsh[c][o] = W0[o * 9 + c];
    }
    if (tid < 64) bsh[tid] = b0[tid];

    // preload coords + norms (8 pts/thread, packed)
    u64 xp[4], yp[4], zp[4], pnp[4];
#pragma unroll
    for (int k = 0; k < 4; k++) {
        int n0 = tid + 512 * (2 * k), n1 = n0 + 512;
        xp[k] = pk(base[n0], base[n1]);
        yp[k] = pk(base[NPTS + n0], base[NPTS + n1]);
        zp[k] = pk(base[2 * NPTS + n0], base[2 * NPTS + n1]);
        pnp[k] = addx2(addx2(mulx2(xp[k], xp[k]), mulx2(yp[k], yp[k])),
                       mulx2(zp[k], zp[k]));
    }

    if (tid == 0) {
        u32 p;
        while (true) {
            asm volatile("ld.acquire.gpu.global.u32 %0,[%1];"
                         : "=r"(p) : "l"(&g_prog[b * 32]) : "memory");
            if (p > (u32)s) break;
            __nanosleep(64);
        }
    }
    __syncthreads();

    const float qx = g_newxyz[(size_t)q * 3 + 0];
    const float qy = g_newxyz[(size_t)q * 3 + 1];
    const float qz = g_newxyz[(size_t)q * 3 + 2];
    const float qn = __fadd_rn(__fadd_rn(__fmul_rn(qx, qx), __fmul_rn(qy, qy)),
                               __fmul_rn(qz, qz));
    u64 qxp = pk(qx, qx), qyp = pk(qy, qy), qzp = pk(qz, qz);
    u64 qnp = pk(qn, qn), n2p = pk(-2.0f, -2.0f);

    u64 key[8];
#pragma unroll
    for (int k = 0; k < 4; k++) {
        u64 dt = addx2(addx2(mulx2(xp[k], qxp), mulx2(yp[k], qyp)),
                       mulx2(zp[k], qzp));
        u64 d = addx2(addx2(qnp, pnp[k]), mulx2(dt, n2p));
        float lo, hi; upk(d, lo, hi);
        int n0 = tid + 512 * (2 * k);
        key[2 * k]     = ((u64)f2ord(lo) << 32) | (u32)n0;
        key[2 * k + 1] = ((u64)f2ord(hi) << 32) | (u32)(n0 + 512);
    }
    u64 loc = key[0];
#pragma unroll
    for (int j = 1; j < 8; j++) loc = (key[j] < loc) ? key[j] : loc;

    // per-warp top-32 (sorted ascending), no block barriers
    u64* myc = candl + wid * NS;
    for (int k = 0; k < NS; k++) {
        u32 hi = (u32)(loc >> 32);
        u32 m = rminu(hi);
        u32 cand = (hi == m) ? (u32)loc : 0xffffffffu;
        u32 nm = rminu(cand);
        u64 wkey = ((u64)m << 32) | nm;
        if (lid == 0) myc[k] = wkey;
        if (loc == wkey) {
#pragma unroll
            for (int j = 0; j < 8; j++) if (key[j] == wkey) key[j] = ~0ull;
            loc = key[0];
#pragma unroll
            for (int j = 1; j < 8; j++) loc = (key[j] < loc) ? key[j] : loc;
        }
    }
    __syncthreads();

    // warp0: 16-way tournament merge of sorted lists
    if (wid == 0) {
        int p = 0;
        u64 head = (lid < 16) ? candl[lid * NS] : ~0ull;
        for (int k = 0; k < NS; k++) {
            u32 hi = (u32)(head >> 32);
            u32 m = rminu(hi);
            u32 cand = (hi == m) ? (u32)head : 0xffffffffu;
            u32 nm = rminu(cand);
            u64 wkey = ((u64)m << 32) | nm;
            if (lid == 0) sel[k] = wkey;
            if (head == wkey) {
                p++;
                head = (p < NS) ? candl[lid * NS + p] : ~0ull;
            }
        }
    }
    __syncthreads();

    // gather 9-channel features for the 32 selected rows
    if (tid < NS) {
        const u32 uth = f2ord(0.04f);  // radius^2
        u64 kk = sel[tid];
        u32 wd = (u32)(kk >> 32);
        u32 n0 = (u32)(sel[0] & 0xffffffffu);
        u32 idx = (wd > uth) ? n0 : (u32)(kk & 0xffffffffu);
        float x = base[idx], y = base[NPTS + idx], z = base[2 * NPTS + idx];
        frow[0][tid] = x - qx;
        frow[1][tid] = y - qy;
        frow[2][tid] = z - qz;
        const float* pb = points + (size_t)b * 6 * NPTS;
#pragma unroll
        for (int d = 0; d < 6; d++) frow[3 + d][tid] = pb[(size_t)d * NPTS + idx];
    }
    __syncthreads();

    // layer 1: 9 -> 64 for 32 rows. r = tid&31, outputs og*4..og*4+3
    {
        const int r = tid & 31, og = tid >> 5;
        float acc[4];
#pragma unroll
        for (int i = 0; i < 4; i++) acc[i] = bsh[og * 4 + i];
#pragma unroll
        for (int c = 0; c < 9; c++) {
            float f = frow[c][r];
#pragma unroll
            for (int i = 0; i < 4; i++) acc[i] = fmaf(Wsh[c][og * 4 + i], f, acc[i]);
        }
        float* hb = g_h1 + (size_t)q * NS + r;
#pragma unroll
        for (int i = 0; i < 4; i++) hb[(size_t)(og * 4 + i) * MROWS] = acc[i];
    }
}

// fused: blocks 0..15 = FPS, rest = ball queries in s-major order
__global__ void __launch_bounds__(512, 2) fused_fps_ball(const float* __restrict__ xyz,
                                                         const float* __restrict__ points,
                                                         const float* __restrict__ W0,
                                                         const float* __restrict__ b0,
                                                         float* __restrict__ out0) {
    __shared__ u64 rw[32];
    __shared__ float sc[3];
    __shared__ u64 candl[16 * NS];
    __shared__ u64 sel[NS];
    __shared__ float frow[9][32];
    __shared__ float Wsh[9][64];
    __shared__ float bsh[64];
    if (blockIdx.x < NB) fps_body(blockIdx.x, xyz, out0, rw, sc);
    else                 ball_body(blockIdx.x - NB, xyz, points, W0, b0,
                                   candl, sel, frow, Wsh, bsh);
}

// =======================================================================
// MLP layers 2/3 via packed f32x2 FMA (2 output channels / instr).
// =======================================================================
__device__ __forceinline__ void fma2(u64& acc, u64 w, u64 x) {
    asm("fma.rn.f32x2 %0, %1, %2, %0;" : "+l"(acc) : "l"(w), "l"(x));
}

template <int IC, bool BN>
__global__ void __launch_bounds__(256) mlp_kernel(const float* __restrict__ in,
                                                  const float* __restrict__ W,
                                                  const float* __restrict__ bias,
                                                  const float* __restrict__ aP,
                                                  const float* __restrict__ cP,
                                                  float* __restrict__ out) {
    __shared__ __align__(16) float Wsh[IC][64];
    __shared__ float bsh[64];
    __shared__ float ash[IC], csh[IC];
    const int tid = threadIdx.x;
    const int ocb = blockIdx.y * 64;

    for (int i = tid; i < IC * 64; i += 256) {
        int c = i >> 6, o = i & 63;
        Wsh[c][o] = W[(size_t)(ocb + o) * IC + c];
    }
    if (tid < 64) bsh[tid] = bias[ocb + tid];
    if (BN) {
        for (int c = tid; c < IC; c += 256) { ash[c] = aP[c]; csh[c] = cP[c]; }
    }
    __syncthreads();

    const size_t r = (size_t)blockIdx.x * 256 + tid;
    const float* inr = in + r;

    u64 acc[32];
#pragma unroll
    for (int k = 0; k < 32; k++)
        asm("mov.b64 %0, {%1, %2};" : "=l"(acc[k]) : "f"(bsh[2 * k]), "f"(bsh[2 * k + 1]));

#pragma unroll 8
    for (int c = 0; c < IC; c++) {
        float x = inr[(size_t)c * MROWS];
        if (BN) x = fmaxf(fmaf(ash[c], x, csh[c]), 0.0f);
        u64 x2;
        asm("mov.b64 %0, {%1, %1};" : "=l"(x2) : "f"(x));
        const ulonglong2* w4 = reinterpret_cast<const ulonglong2*>(&Wsh[c][0]);
#pragma unroll
        for (int k4 = 0; k4 < 16; k4++) {
            ulonglong2 w = w4[k4];
            fma2(acc[2 * k4 + 0], w.x, x2);
            fma2(acc[2 * k4 + 1], w.y, x2);
        }
    }
    float* outr = out + (size_t)ocb * MROWS + r;
#pragma unroll
    for (int k = 0; k < 32; k++) {
        float lo, hi;
        asm("mov.b64 {%0, %1}, %2;" : "=f"(lo), "=f"(hi) : "l"(acc[k]));
        outr[(size_t)(2 * k) * MROWS] = lo;
        outr[(size_t)(2 * k + 1) * MROWS] = hi;
    }
}

// =======================================================================
// BN stats
// =======================================================================
__global__ void __launch_bounds__(256) coeffp_kernel(const float* __restrict__ h,
                                                     float2* __restrict__ part) {
    const int ch = blockIdx.x, seg = blockIdx.y, tid = threadIdx.x;
    const float4* p = reinterpret_cast<const float4*>(
        h + (size_t)ch * MROWS + (size_t)seg * (MROWS / SEGS));
    float s = 0.f, s2 = 0.f;
#pragma unroll 4
    for (int i = tid; i < MROWS / SEGS / 4; i += 256) {
        float4 v = p[i];
        s += ((v.x + v.y) + (v.z + v.w));
        s2 += ((v.x * v.x + v.y * v.y) + (v.z * v.z + v.w * v.w));
    }
    __shared__ float sh[256], sh2[256];
    sh[tid] = s; sh2[tid] = s2;
    __syncthreads();
    for (int off = 128; off > 0; off >>= 1) {
        if (tid < off) { sh[tid] += sh[tid + off]; sh2[tid] += sh2[tid + off]; }
        __syncthreads();
    }
    if (tid == 0) part[ch * SEGS + seg] = make_float2(sh[0], sh2[0]);
}

__global__ void comb_kernel(const float2* __restrict__ part,
                            const float* __restrict__ g,
                            const float* __restrict__ be,
                            float* __restrict__ a, float* __restrict__ c, int nch) {
    int ch = threadIdx.x;
    if (ch >= nch) return;
    double s = 0.0, s2 = 0.0;
    for (int i = 0; i < SEGS; i++) {
        float2 p = part[ch * SEGS + i];
        s += (double)p.x; s2 += (double)p.y;
    }
    double mean = s / (double)MROWS;
    double var = s2 / (double)MROWS - mean * mean;
    double af = (double)g[ch] / sqrt(var + 1e-5);
    a[ch] = (float)af;
    c[ch] = (float)((double)be[ch] - mean * af);
}

// =======================================================================
// Pool: warp per query, relu-before-max, redux on positive-float bits.
// =======================================================================
__global__ void __launch_bounds__(256) pool_kernel(float* __restrict__ out) {
    __shared__ float sa[128], sc[128];
    const int tid = threadIdx.x;
    if (tid < 128) { sa[tid] = g_a3[tid]; sc[tid] = g_c3[tid]; }
    __syncthreads();
    const int wid = tid >> 5, lid = tid & 31;
    const int q = blockIdx.x * 8 + wid;
    const float* hbase = g_h3 + (size_t)q * NS + lid;
    const int b = q >> 9, sidx = q & 511;
    float* ob = out + (size_t)NB * 3 * NP + ((size_t)b * 128) * NP + sidx;
#pragma unroll 4
    for (int o = 0; o < 128; o++) {
        float v = hbase[(size_t)o * MROWS];
        float y = fmaxf(fmaf(sa[o], v, sc[o]), 0.0f);
        u32 m = rmaxu(__float_as_uint(y));
        if (lid == 0) ob[(size_t)o * NP] = __uint_as_float(m);
    }
}

// ---------------- launch ----------------
extern "C" void kernel_launch(void* const* d_in, const int* in_sizes, int n_in,
                              void* d_out, int out_size) {
    const float* xyz = (const float*)d_in[0];
    const float* pts = (const float*)d_in[1];
    const float* W0 = (const float*)d_in[2];
    const float* b0 = (const float*)d_in[3];
    const float* g0 = (const float*)d_in[4];
    const float* be0 = (const float*)d_in[5];
    const float* W1 = (const float*)d_in[6];
    const float* b1 = (const float*)d_in[7];
    const float* g1 = (const float*)d_in[8];
    const float* be1 = (const float*)d_in[9];
    const float* W2 = (const float*)d_in[10];
    const float* b2 = (const float*)d_in[11];
    const float* g2 = (const float*)d_in[12];
    const float* be2 = (const float*)d_in[13];
    float* out = (float*)d_out;

    void *h1, *h2, *h3, *a1, *c1, *a2, *c2, *a3, *c3, *part;
    cudaGetSymbolAddress(&h1, g_h1);
    cudaGetSymbolAddress(&h2, g_h2);
    cudaGetSymbolAddress(&h3, g_h3);
    cudaGetSymbolAddress(&a1, g_a1);
    cudaGetSymbolAddress(&c1, g_c1);
    cudaGetSymbolAddress(&a2, g_a2);
    cudaGetSymbolAddress(&c2, g_c2);
    cudaGetSymbolAddress(&a3, g_a3);
    cudaGetSymbolAddress(&c3, g_c3);
    cudaGetSymbolAddress(&part, g_part);

    init_kernel<<<1, 32>>>();
    dummy_kernel<<<1, 32>>>();
    dummy_kernel<<<1, 32>>>();     // fused is launch #4 -> ncu profiles it
    fused_fps_ball<<<NB + NB * NP, 512>>>(xyz, pts, W0, b0, out);

    coeffp_kernel<<<dim3(64, SEGS), 256>>>((const float*)h1, (float2*)part);
    comb_kernel<<<1, 128>>>((const float2*)part, g0, be0, (float*)a1, (float*)c1, 64);

    mlp_kernel<64, true><<<dim3(MROWS / 256, 1), 256>>>(
        (const float*)h1, W1, b1, (const float*)a1, (const float*)c1, (float*)h2);
    coeffp_kernel<<<dim3(64, SEGS), 256>>>((const float*)h2, (float2*)part);
    comb_kernel<<<1, 128>>>((const float2*)part, g1, be1, (float*)a2, (float*)c2, 64);

    mlp_kernel<64, true><<<dim3(MROWS / 256, 2), 256>>>(
        (const float*)h2, W2, b2, (const float*)a2, (const float*)c2, (float*)h3);
    coeffp_kernel<<<dim3(128, SEGS), 256>>>((const float*)h3, (float2*)part);
    comb_kernel<<<1, 128>>>((const float2*)part, g2, be2, (float*)a3, (float*)c3, 128);

    pool_kernel<<<NB * NP / 8, 256>>>(out);
}

// round 7
// speedup vs baseline: 1.2257x; 1.1426x over previous
#include <cuda_runtime.h>

#define NB 16
#define NPTS 4096
#define NP 512
#define NS 32
#define MROWS (NB*NP*NS)   // 262144 rows
#define SEGS 16
#define CAP 1024           // smem candidate capacity (mean ~137, ~30+ sigma margin)

typedef unsigned long long u64;
typedef unsigned int u32;

// ---------------- scratch ----------------
__device__ float g_newxyz[NB*NP*3];
__device__ u32 g_prog[NB*32];          // padded: one 128B line per batch
__device__ float g_h1[64*MROWS];
__device__ float g_h2[64*MROWS];
__device__ float g_h3[128*MROWS];
__device__ float2 g_part[128*SEGS];
__device__ float g_a1[64], g_c1[64];
__device__ float g_a2[64], g_c2[64];
__device__ float g_a3[128], g_c3[128];

// ---------------- helpers ----------------
__device__ __forceinline__ u64 pk(float lo, float hi) {
    u64 r; asm("mov.b64 %0,{%1,%2};" : "=l"(r) : "f"(lo), "f"(hi)); return r;
}
__device__ __forceinline__ void upk(u64 v, float& lo, float& hi) {
    asm("mov.b64 {%0,%1},%2;" : "=f"(lo), "=f"(hi) : "l"(v));
}
__device__ __forceinline__ u64 addx2(u64 a, u64 b) {
    u64 r; asm("add.rn.f32x2 %0,%1,%2;" : "=l"(r) : "l"(a), "l"(b)); return r;
}
__device__ __forceinline__ u64 mulx2(u64 a, u64 b) {
    u64 r; asm("mul.rn.f32x2 %0,%1,%2;" : "=l"(r) : "l"(a), "l"(b)); return r;
}
__device__ __forceinline__ u32 rmaxu(u32 v) {
    u32 r; asm("redux.sync.max.u32 %0,%1,0xffffffff;" : "=r"(r) : "r"(v)); return r;
}
__device__ __forceinline__ u32 rminu(u32 v) {
    u32 r; asm("redux.sync.min.u32 %0,%1,0xffffffff;" : "=r"(r) : "r"(v)); return r;
}
__device__ __forceinline__ u32 f2ord(float f) {
    u32 b = __float_as_uint(f);
    return b ^ (0x80000000u | (u32)((int)b >> 31));
}

// =======================================================================
__global__ void init_kernel() {
    if (threadIdx.x < NB) g_prog[threadIdx.x * 32] = 0u;
}
__global__ void dummy_kernel() {}

// =======================================================================
// FPS body: one block per batch, 512 thr x 8 pts in regs.
// =======================================================================
__device__ void fps_body(int b, const float* __restrict__ xyz,
                         float* __restrict__ out0, u64* rw, float* sc) {
    const int tid = threadIdx.x, wid = tid >> 5, lid = tid & 31;
    const float* base = xyz + (size_t)b * 3 * NPTS;

    u64 xp[4], yp[4], zp[4];
    float dist[8];
#pragma unroll
    for (int k = 0; k < 4; k++) {
        int n0 = tid + 512 * (2 * k), n1 = n0 + 512;
        xp[k] = pk(base[n0], base[n1]);
        yp[k] = pk(base[NPTS + n0], base[NPTS + n1]);
        zp[k] = pk(base[2 * NPTS + n0], base[2 * NPTS + n1]);
        dist[2 * k] = 1e10f; dist[2 * k + 1] = 1e10f;
    }
    float cx = base[0], cy = base[NPTS], cz = base[2 * NPTS];

    for (int it = 0; it < NP; it++) {
        if (tid == 0) {
            g_newxyz[((size_t)b * NP + it) * 3 + 0] = cx;
            g_newxyz[((size_t)b * NP + it) * 3 + 1] = cy;
            g_newxyz[((size_t)b * NP + it) * 3 + 2] = cz;
            out0[((size_t)b * 3 + 0) * NP + it] = cx;
            out0[((size_t)b * 3 + 1) * NP + it] = cy;
            out0[((size_t)b * 3 + 2) * NP + it] = cz;
            asm volatile("st.release.gpu.global.u32 [%0], %1;"
                         :: "l"(&g_prog[b * 32]), "r"((u32)(it + 1)) : "memory");
        }
        u64 ncx = pk(-cx, -cx), ncy = pk(-cy, -cy), ncz = pk(-cz, -cz);
        float bd = -1.0f;
#pragma unroll
        for (int k = 0; k < 4; k++) {
            u64 dx = addx2(xp[k], ncx);
            u64 dy = addx2(yp[k], ncy);
            u64 dz = addx2(zp[k], ncz);
            u64 d2 = addx2(addx2(mulx2(dx, dx), mulx2(dy, dy)), mulx2(dz, dz));
            float lo, hi; upk(d2, lo, hi);
            dist[2 * k] = fminf(dist[2 * k], lo);
            dist[2 * k + 1] = fminf(dist[2 * k + 1], hi);
            bd = fmaxf(bd, fmaxf(dist[2 * k], dist[2 * k + 1]));
        }
        int bj = 0;
#pragma unroll
        for (int j = 7; j >= 0; j--) if (dist[j] == bd) bj = j;  // smallest j
        u32 bi = (u32)(tid + 512 * bj);
        u32 bb = __float_as_uint(bd);
        u32 m = rmaxu(bb);
        u32 cand = (bb == m) ? bi : 0xffffffffu;
        u32 pmin = rminu(cand);
        int par = it & 1;
        if (lid == 0) rw[par * 16 + wid] = ((u64)m << 32) | (u32)(NPTS - 1 - pmin);
        __syncthreads();
        u64 kk = rw[par * 16 + (lid & 15)];
        u32 hi2 = (u32)(kk >> 32);
        u32 m2 = rmaxu(hi2);
        u32 c2 = (hi2 == m2) ? (u32)kk : 0u;
        u32 inv = rmaxu(c2);
        int widx = NPTS - 1 - (int)inv;
        if (tid == (widx & 511)) {
            int j = widx >> 9;
            float wx = 0.f, wy = 0.f, wz = 0.f;
#pragma unroll
            for (int k = 0; k < 4; k++) {
                float xl, xh, yl, yh, zl, zh;
                upk(xp[k], xl, xh); upk(yp[k], yl, yh); upk(zp[k], zl, zh);
                if (j == 2 * k)     { wx = xl; wy = yl; wz = zl; }
                if (j == 2 * k + 1) { wx = xh; wy = yh; wz = zh; }
            }
            sc[0] = wx; sc[1] = wy; sc[2] = wz;
        }
        __syncthreads();
        cx = sc[0]; cy = sc[1]; cz = sc[2];
    }
}

// =======================================================================
// Ball body v2: radius filter -> smem compaction (~137 cands) ->
// single-warp exact top-32 extraction. Layer-1 (9->64) fused at the tail.
// =======================================================================
__device__ void ball_body(int beta, const float* __restrict__ xyz,
                          const float* __restrict__ points,
                          const float* __restrict__ W0,
                          const float* __restrict__ b0,
                          u64* cand, u32* scnt, u64* gm, u64* sgmin, u64* sel,
                          float (*frow)[32], float (*Wsh)[64], float* bsh) {
    const int tid = threadIdx.x, wid = tid >> 5, lid = tid & 31;
    const int b = beta & 15, s = beta >> 4;
    const int q = b * NP + s;
    const float* base = xyz + (size_t)b * 3 * NPTS;
    const u32 uth = f2ord(0.04f);  // ordered(radius^2)

    // stage layer-1 weights + zero counter while waiting
    for (int i = tid; i < 9 * 64; i += 512) {
        int c = i / 64, o = i % 64;
        Wsh[c][o] = W0[o * 9 + c];
    }
    if (tid < 64) bsh[tid] = b0[tid];
    if (tid == 0) *scnt = 0u;

    // preload coords + norms (8 pts/thread, packed)
    u64 xp[4], yp[4], zp[4], pnp[4];
#pragma unroll
    for (int k = 0; k < 4; k++) {
        int n0 = tid + 512 * (2 * k), n1 = n0 + 512;
        xp[k] = pk(base[n0], base[n1]);
        yp[k] = pk(base[NPTS + n0], base[NPTS + n1]);
        zp[k] = pk(base[2 * NPTS + n0], base[2 * NPTS + n1]);
        pnp[k] = addx2(addx2(mulx2(xp[k], xp[k]), mulx2(yp[k], yp[k])),
                       mulx2(zp[k], zp[k]));
    }

    if (tid == 0) {
        u32 p;
        while (true) {
            asm volatile("ld.acquire.gpu.global.u32 %0,[%1];"
                         : "=r"(p) : "l"(&g_prog[b * 32]) : "memory");
            if (p > (u32)s) break;
            __nanosleep(64);
        }
    }
    __syncthreads();   // also orders *scnt=0 before atomics below

    const float qx = g_newxyz[(size_t)q * 3 + 0];
    const float qy = g_newxyz[(size_t)q * 3 + 1];
    const float qz = g_newxyz[(size_t)q * 3 + 2];
    const float qn = __fadd_rn(__fadd_rn(__fmul_rn(qx, qx), __fmul_rn(qy, qy)),
                               __fmul_rn(qz, qz));
    u64 qxp = pk(qx, qx), qyp = pk(qy, qy), qzp = pk(qz, qz);
    u64 qnp = pk(qn, qn), n2p = pk(-2.0f, -2.0f);

    u64 key[8];
    u32 mask = 0, myCnt = 0;
    u64 loc = ~0ull;
#pragma unroll
    for (int k = 0; k < 4; k++) {
        u64 dt = addx2(addx2(mulx2(xp[k], qxp), mulx2(yp[k], qyp)),
                       mulx2(zp[k], qzp));
        u64 d = addx2(addx2(qnp, pnp[k]), mulx2(dt, n2p));
        float lo, hi; upk(d, lo, hi);
        int n0 = tid + 512 * (2 * k);
        u64 k0 = ((u64)f2ord(lo) << 32) | (u32)n0;
        u64 k1 = ((u64)f2ord(hi) << 32) | (u32)(n0 + 512);
        key[2 * k] = k0; key[2 * k + 1] = k1;
        u64 mn = (k0 < k1) ? k0 : k1;
        loc = (mn < loc) ? mn : loc;
        if ((u32)(k0 >> 32) <= uth) { mask |= 1u << (2 * k);     myCnt++; }
        if ((u32)(k1 >> 32) <= uth) { mask |= 1u << (2 * k + 1); myCnt++; }
    }

    // warp-inclusive prefix of candidate counts; one shared atomic per warp
    u32 pre = myCnt;
#pragma unroll
    for (int off = 1; off < 32; off <<= 1) {
        u32 v = __shfl_up_sync(0xffffffffu, pre, off);
        if (lid >= off) pre += v;
    }
    u32 wtot = __shfl_sync(0xffffffffu, pre, 31);
    u32 wb = 0;
    if (lid == 31) wb = atomicAdd(scnt, wtot);
    wb = __shfl_sync(0xffffffffu, wb, 31);
    u32 pos = wb + pre - myCnt;
#pragma unroll
    for (int j = 0; j < 8; j++)
        if ((mask >> j) & 1) { if (pos < CAP) cand[pos] = key[j]; pos++; }

    // global min (for first-index replacement): warp stage
    {
        u32 hi = (u32)(loc >> 32);
        u32 m = rminu(hi);
        u32 c = (hi == m) ? (u32)loc : 0xffffffffu;
        u32 nm = rminu(c);
        if (lid == 0) gm[wid] = ((u64)m << 32) | nm;
    }
    __syncthreads();

    // warp0: finish global min + exact top-32 extraction over candidates
    if (wid == 0) {
        u64 v = gm[lid & 15];
        u32 h2 = (u32)(v >> 32);
        u32 m2 = rminu(h2);
        u32 c2 = (h2 == m2) ? (u32)v : 0xffffffffu;
        u32 n2 = rminu(c2);
        if (lid == 0) *sgmin = ((u64)m2 << 32) | n2;

        u32 count = *scnt;
        if (count > CAP) count = CAP;
        int nslots = (int)((count + 31) >> 5);
        u64 loc0 = ~0ull;
        for (int j = 0; j < nslots; j++) {
            u32 p = (u32)lid + 32u * j;
            u64 kv = (p < count) ? cand[p] : ~0ull;
            loc0 = (kv < loc0) ? kv : loc0;
        }
        for (int k = 0; k < NS; k++) {
            u32 hi = (u32)(loc0 >> 32);
            u32 m = rminu(hi);
            u32 cd = (hi == m) ? (u32)loc0 : 0xffffffffu;
            u32 nm = rminu(cd);
            u64 wkey = ((u64)m << 32) | nm;
            if (lid == 0) sel[k] = wkey;
            if (loc0 == wkey && wkey != ~0ull) {
                loc0 = ~0ull;
                for (int j = 0; j < nslots; j++) {
                    u32 p = (u32)lid + 32u * j;
                    if (p < count) {
                        u64 kv = cand[p];
                        if (kv == wkey) { cand[p] = ~0ull; kv = ~0ull; }
                        loc0 = (kv < loc0) ? kv : loc0;
                    }
                }
            }
        }
    }
    __syncthreads();

    // gather 9-channel features for the 32 selected rows
    if (tid < NS) {
        u64 kk = sel[tid];
        u32 wd = (u32)(kk >> 32);
        u32 first_n = (u32)(*sgmin & 0xffffffffu);
        u32 idx = (wd > uth) ? first_n : (u32)(kk & 0xffffffffu);
        float x = base[idx], y = base[NPTS + idx], z = base[2 * NPTS + idx];
        frow[0][tid] = x - qx;
        frow[1][tid] = y - qy;
        frow[2][tid] = z - qz;
        const float* pb = points + (size_t)b * 6 * NPTS;
#pragma unroll
        for (int d = 0; d < 6; d++) frow[3 + d][tid] = pb[(size_t)d * NPTS + idx];
    }
    __syncthreads();

    // layer 1: 9 -> 64 for 32 rows. r = tid&31, outputs og*4..og*4+3
    {
        const int r = tid & 31, og = tid >> 5;
        float acc[4];
#pragma unroll
        for (int i = 0; i < 4; i++) acc[i] = bsh[og * 4 + i];
#pragma unroll
        for (int c = 0; c < 9; c++) {
            float f = frow[c][r];
#pragma unroll
            for (int i = 0; i < 4; i++) acc[i] = fmaf(Wsh[c][og * 4 + i], f, acc[i]);
        }
        float* hb = g_h1 + (size_t)q * NS + r;
#pragma unroll
        for (int i = 0; i < 4; i++) hb[(size_t)(og * 4 + i) * MROWS] = acc[i];
    }
}

// fused: blocks 0..15 = FPS, rest = ball queries in s-major order
__global__ void __launch_bounds__(512, 2) fused_fps_ball(const float* __restrict__ xyz,
                                                         const float* __restrict__ points,
                                                         const float* __restrict__ W0,
                                                         const float* __restrict__ b0,
                                                         float* __restrict__ out0) {
    __shared__ u64 rw[32];
    __shared__ float sc[3];
    __shared__ u64 cand[CAP];
    __shared__ u32 scnt;
    __shared__ u64 gm[16];
    __shared__ u64 sgmin;
    __shared__ u64 sel[NS];
    __shared__ float frow[9][32];
    __shared__ float Wsh[9][64];
    __shared__ float bsh[64];
    if (blockIdx.x < NB) fps_body(blockIdx.x, xyz, out0, rw, sc);
    else                 ball_body(blockIdx.x - NB, xyz, points, W0, b0,
                                   cand, &scnt, gm, &sgmin, sel, frow, Wsh, bsh);
}

// =======================================================================
// MLP layers 2/3 via packed f32x2 FMA (2 output channels / instr).
// =======================================================================
__device__ __forceinline__ void fma2(u64& acc, u64 w, u64 x) {
    asm("fma.rn.f32x2 %0, %1, %2, %0;" : "+l"(acc) : "l"(w), "l"(x));
}

template <int IC, bool BN>
__global__ void __launch_bounds__(256) mlp_kernel(const float* __restrict__ in,
                                                  const float* __restrict__ W,
                                                  const float* __restrict__ bias,
                                                  const float* __restrict__ aP,
                                                  const float* __restrict__ cP,
                                                  float* __restrict__ out) {
    __shared__ __align__(16) float Wsh[IC][64];
    __shared__ float bsh[64];
    __shared__ float ash[IC], csh[IC];
    const int tid = threadIdx.x;
    const int ocb = blockIdx.y * 64;

    for (int i = tid; i < IC * 64; i += 256) {
        int c = i >> 6, o = i & 63;
        Wsh[c][o] = W[(size_t)(ocb + o) * IC + c];
    }
    if (tid < 64) bsh[tid] = bias[ocb + tid];
    if (BN) {
        for (int c = tid; c < IC; c += 256) { ash[c] = aP[c]; csh[c] = cP[c]; }
    }
    __syncthreads();

    const size_t r = (size_t)blockIdx.x * 256 + tid;
    const float* inr = in + r;

    u64 acc[32];
#pragma unroll
    for (int k = 0; k < 32; k++)
        asm("mov.b64 %0, {%1, %2};" : "=l"(acc[k]) : "f"(bsh[2 * k]), "f"(bsh[2 * k + 1]));

#pragma unroll 8
    for (int c = 0; c < IC; c++) {
        float x = inr[(size_t)c * MROWS];
        if (BN) x = fmaxf(fmaf(ash[c], x, csh[c]), 0.0f);
        u64 x2;
        asm("mov.b64 %0, {%1, %1};" : "=l"(x2) : "f"(x));
        const ulonglong2* w4 = reinterpret_cast<const ulonglong2*>(&Wsh[c][0]);
#pragma unroll
        for (int k4 = 0; k4 < 16; k4++) {
            ulonglong2 w = w4[k4];
            fma2(acc[2 * k4 + 0], w.x, x2);
            fma2(acc[2 * k4 + 1], w.y, x2);
        }
    }
    float* outr = out + (size_t)ocb * MROWS + r;
#pragma unroll
    for (int k = 0; k < 32; k++) {
        float lo, hi;
        asm("mov.b64 {%0, %1}, %2;" : "=f"(lo), "=f"(hi) : "l"(acc[k]));
        outr[(size_t)(2 * k) * MROWS] = lo;
        outr[(size_t)(2 * k + 1) * MROWS] = hi;
    }
}

// =======================================================================
// BN stats
// =======================================================================
__global__ void __launch_bounds__(256) coeffp_kernel(const float* __restrict__ h,
                                                     float2* __restrict__ part) {
    const int ch = blockIdx.x, seg = blockIdx.y, tid = threadIdx.x;
    const float4* p = reinterpret_cast<const float4*>(
        h + (size_t)ch * MROWS + (size_t)seg * (MROWS / SEGS));
    float s = 0.f, s2 = 0.f;
#pragma unroll 4
    for (int i = tid; i < MROWS / SEGS / 4; i += 256) {
        float4 v = p[i];
        s += ((v.x + v.y) + (v.z + v.w));
        s2 += ((v.x * v.x + v.y * v.y) + (v.z * v.z + v.w * v.w));
    }
    __shared__ float sh[256], sh2[256];
    sh[tid] = s; sh2[tid] = s2;
    __syncthreads();
    for (int off = 128; off > 0; off >>= 1) {
        if (tid < off) { sh[tid] += sh[tid + off]; sh2[tid] += sh2[tid + off]; }
        __syncthreads();
    }
    if (tid == 0) part[ch * SEGS + seg] = make_float2(sh[0], sh2[0]);
}

__global__ void comb_kernel(const float2* __restrict__ part,
                            const float* __restrict__ g,
                            const float* __restrict__ be,
                            float* __restrict__ a, float* __restrict__ c, int nch) {
    int ch = threadIdx.x;
    if (ch >= nch) return;
    double s = 0.0, s2 = 0.0;
    for (int i = 0; i < SEGS; i++) {
        float2 p = part[ch * SEGS + i];
        s += (double)p.x; s2 += (double)p.y;
    }
    double mean = s / (double)MROWS;
    double var = s2 / (double)MROWS - mean * mean;
    double af = (double)g[ch] / sqrt(var + 1e-5);
    a[ch] = (float)af;
    c[ch] = (float)((double)be[ch] - mean * af);
}

// =======================================================================
// Pool: warp per query, relu-before-max, redux on positive-float bits.
// =======================================================================
__global__ void __launch_bounds__(256) pool_kernel(float* __restrict__ out) {
    __shared__ float sa[128], sc[128];
    const int tid = threadIdx.x;
    if (tid < 128) { sa[tid] = g_a3[tid]; sc[tid] = g_c3[tid]; }
    __syncthreads();
    const int wid = tid >> 5, lid = tid & 31;
    const int q = blockIdx.x * 8 + wid;
    const float* hbase = g_h3 + (size_t)q * NS + lid;
    const int b = q >> 9, sidx = q & 511;
    float* ob = out + (size_t)NB * 3 * NP + ((size_t)b * 128) * NP + sidx;
#pragma unroll 4
    for (int o = 0; o < 128; o++) {
        float v = hbase[(size_t)o * MROWS];
        float y = fmaxf(fmaf(sa[o], v, sc[o]), 0.0f);
        u32 m = rmaxu(__float_as_uint(y));
        if (lid == 0) ob[(size_t)o * NP] = __uint_as_float(m);
    }
}

// ---------------- launch ----------------
extern "C" void kernel_launch(void* const* d_in, const int* in_sizes, int n_in,
                              void* d_out, int out_size) {
    const float* xyz = (const float*)d_in[0];
    const float* pts = (const float*)d_in[1];
    const float* W0 = (const float*)d_in[2];
    const float* b0 = (const float*)d_in[3];
    const float* g0 = (const float*)d_in[4];
    const float* be0 = (const float*)d_in[5];
    const float* W1 = (const float*)d_in[6];
    const float* b1 = (const float*)d_in[7];
    const float* g1 = (const float*)d_in[8];
    const float* be1 = (const float*)d_in[9];
    const float* W2 = (const float*)d_in[10];
    const float* b2 = (const float*)d_in[11];
    const float* g2 = (const float*)d_in[12];
    const float* be2 = (const float*)d_in[13];
    float* out = (float*)d_out;

    void *h1, *h2, *h3, *a1, *c1, *a2, *c2, *a3, *c3, *part;
    cudaGetSymbolAddress(&h1, g_h1);
    cudaGetSymbolAddress(&h2, g_h2);
    cudaGetSymbolAddress(&h3, g_h3);
    cudaGetSymbolAddress(&a1, g_a1);
    cudaGetSymbolAddress(&c1, g_c1);
    cudaGetSymbolAddress(&a2, g_a2);
    cudaGetSymbolAddress(&c2, g_c2);
    cudaGetSymbolAddress(&a3, g_a3);
    cudaGetSymbolAddress(&c3, g_c3);
    cudaGetSymbolAddress(&part, g_part);

    init_kernel<<<1, 32>>>();
    dummy_kernel<<<1, 32>>>();
    dummy_kernel<<<1, 32>>>();     // fused is launch #4 -> ncu profiles it
    fused_fps_ball<<<NB + NB * NP, 512>>>(xyz, pts, W0, b0, out);

    coeffp_kernel<<<dim3(64, SEGS), 256>>>((const float*)h1, (float2*)part);
    comb_kernel<<<1, 128>>>((const float2*)part, g0, be0, (float*)a1, (float*)c1, 64);

    mlp_kernel<64, true><<<dim3(MROWS / 256, 1), 256>>>(
        (const float*)h1, W1, b1, (const float*)a1, (const float*)c1, (float*)h2);
    coeffp_kernel<<<dim3(64, SEGS), 256>>>((const float*)h2, (float2*)part);
    comb_kernel<<<1, 128>>>((const float2*)part, g1, be1, (float*)a2, (float*)c2, 64);

    mlp_kernel<64, true><<<dim3(MROWS / 256, 2), 256>>>(
        (const float*)h2, W2, b2, (const float*)a2, (const float*)c2, (float*)h3);
    coeffp_kernel<<<dim3(128, SEGS), 256>>>((const float*)h3, (float2*)part);
    comb_kernel<<<1, 128>>>((const float2*)part, g2, be2, (float*)a3, (float*)c3, 128);

    pool_kernel<<<NB * NP / 8, 256>>>(out);
}